// round 5
// baseline (speedup 1.0000x reference)
#include <cuda_runtime.h>
#include <math.h>

// Problem constants (from reference): x:(N,D,L), out:(N,D,K)
#define N_ 128
#define D_ 512
#define L_ 512
#define K_ 512
#define M_ (N_ * D_)   // 65536 GEMM rows

// Precomputed operands (static device globals: allocation-free scratch)
__device__ float g_w[D_ * L_];     // sigma-scaled Hann-family window, (D,L)
__device__ float g_cos[L_ * K_];   // cos basis, (L,K)
__device__ float g_sin[L_ * K_];   // sin basis, (L,K)

// ---------------------------------------------------------------------------
// Precompute: window w[d,l] = (a[d] - (1-a[d])cos(2pi l/(L-1))) * exp(sigma[d]/(L-1))
//             basis  cos/sin( (2pi/(L-1)) * l * k )
// Matches jax fp32 arithmetic: angle = fp32(2pi/511) * fp32(l*k), l*k < 2^24 exact.
// ---------------------------------------------------------------------------
__global__ void precompute_kernel(const float* __restrict__ a,
                                  const float* __restrict__ sigma) {
    const int idx = blockIdx.x * blockDim.x + threadIdx.x;
    const float c = (float)(6.283185307179586 / 511.0);  // 2*pi / (L-1)

    if (idx < L_ * K_) {
        const int l = idx / K_;
        const int k = idx - l * K_;
        float s, cc;
        sincosf(c * (float)(l * k), &s, &cc);
        g_cos[idx] = cc;
        g_sin[idx] = s;
    }
    if (idx < D_ * L_) {
        const int d = idx / L_;
        const int l = idx - d * L_;
        const float ad = a[d];
        const float w = ad - (1.0f - ad) * cosf(c * (float)l);
        g_w[idx] = w * expf(sigma[d] * (1.0f / 511.0f));
    }
}

// ---------------------------------------------------------------------------
// Fused dual-GEMM + magnitude:
//   out[row, k] = sqrt( (xw[row,:] . cos[:,k])^2 + (xw[row,:] . sin[:,k])^2 )
// where xw[row, l] = x[row, l] * g_w[row % D, l], row = n*D + d.
// BM=128, BN=64, BK=16; 256 threads; 8x4 micro-tile, two accumulator banks.
// ---------------------------------------------------------------------------
#define BM 128
#define BN 64
#define BK 16
#define TM 8
#define TN 4

__global__ __launch_bounds__(256, 2)
void spectro_gemm_kernel(const float* __restrict__ x, float* __restrict__ out) {
    __shared__ float As[BK][BM];   // A tile, k-major (stride-1 in m for compute reads)
    __shared__ float Bc[BK][BN];
    __shared__ float Bs[BK][BN];

    const int row0 = blockIdx.y * BM;
    const int col0 = blockIdx.x * BN;
    const int tid  = threadIdx.x;

    // A-load mapping: 2 passes of 64 rows x 16 cols (float4 per thread per pass)
    const int ar = tid >> 2;            // 0..63
    const int ac = (tid & 3) << 2;      // 0,4,8,12
    // B-load mapping: 16 rows x 64 cols (float4 per thread per matrix)
    const int br = tid >> 4;            // 0..15
    const int bcol = (tid & 15) << 2;   // 0..60

    // Compute mapping: 16x16 thread grid
    const int tx = tid & 15;            // column group -> n0
    const int ty = tid >> 4;            // row group    -> m0
    const int m0 = ty * TM;
    const int n0 = tx * TN;

    float accR[TM][TN];
    float accI[TM][TN];
#pragma unroll
    for (int i = 0; i < TM; ++i)
#pragma unroll
        for (int j = 0; j < TN; ++j) { accR[i][j] = 0.0f; accI[i][j] = 0.0f; }

    for (int kt = 0; kt < L_; kt += BK) {
        // ---- load A tile (window fused) ----
#pragma unroll
        for (int half = 0; half < 2; ++half) {
            const int r   = ar + half * 64;
            const int row = row0 + r;
            const int d   = row & (D_ - 1);
            const float4 xv = *(const float4*)(x   + (size_t)row * L_ + kt + ac);
            const float4 wv = *(const float4*)(g_w + (size_t)d   * L_ + kt + ac);
            As[ac + 0][r] = xv.x * wv.x;
            As[ac + 1][r] = xv.y * wv.y;
            As[ac + 2][r] = xv.z * wv.z;
            As[ac + 3][r] = xv.w * wv.w;
        }
        // ---- load B tiles (cos & sin) ----
        {
            const size_t boff = (size_t)(kt + br) * K_ + col0 + bcol;
            *(float4*)&Bc[br][bcol] = *(const float4*)(g_cos + boff);
            *(float4*)&Bs[br][bcol] = *(const float4*)(g_sin + boff);
        }
        __syncthreads();

        // ---- compute ----
#pragma unroll
        for (int k = 0; k < BK; ++k) {
            float af[TM];
            const float4 a0 = *(const float4*)&As[k][m0];
            const float4 a1 = *(const float4*)&As[k][m0 + 4];
            af[0] = a0.x; af[1] = a0.y; af[2] = a0.z; af[3] = a0.w;
            af[4] = a1.x; af[5] = a1.y; af[6] = a1.z; af[7] = a1.w;
            const float4 bcv = *(const float4*)&Bc[k][n0];
            const float4 bsv = *(const float4*)&Bs[k][n0];
            const float bcf[TN] = {bcv.x, bcv.y, bcv.z, bcv.w};
            const float bsf[TN] = {bsv.x, bsv.y, bsv.z, bsv.w};
#pragma unroll
            for (int i = 0; i < TM; ++i) {
#pragma unroll
                for (int j = 0; j < TN; ++j) {
                    accR[i][j] = fmaf(af[i], bcf[j], accR[i][j]);
                    accI[i][j] = fmaf(af[i], bsf[j], accI[i][j]);
                }
            }
        }
        __syncthreads();
    }

    // ---- epilogue: magnitude, vectorized store ----
#pragma unroll
    for (int i = 0; i < TM; ++i) {
        const int row = row0 + m0 + i;
        float4 o;
        o.x = sqrtf(fmaf(accR[i][0], accR[i][0], accI[i][0] * accI[i][0]));
        o.y = sqrtf(fmaf(accR[i][1], accR[i][1], accI[i][1] * accI[i][1]));
        o.z = sqrtf(fmaf(accR[i][2], accR[i][2], accI[i][2] * accI[i][2]));
        o.w = sqrtf(fmaf(accR[i][3], accR[i][3], accI[i][3] * accI[i][3]));
        *(float4*)(out + (size_t)row * K_ + col0 + n0) = o;
    }
}

// ---------------------------------------------------------------------------
extern "C" void kernel_launch(void* const* d_in, const int* in_sizes, int n_in,
                              void* d_out, int out_size) {
    const float* x     = (const float*)d_in[0];  // (N, D, L) float32
    const float* a     = (const float*)d_in[1];  // (D,)      float32
    const float* sigma = (const float*)d_in[2];  // (D,)      float32
    float* out = (float*)d_out;                  // (N, D, K) float32

    // Precompute basis + window (covers max(L*K, D*L) = 262144 elements)
    precompute_kernel<<<(L_ * K_ + 255) / 256, 256>>>(a, sigma);

    // Fused dual-GEMM + magnitude
    dim3 grid(K_ / BN, M_ / BM);   // (8, 512)
    spectro_gemm_kernel<<<grid, 256>>>(x, out);
}

// round 7
// speedup vs baseline: 2.2613x; 2.2613x over previous
#include <cuda_runtime.h>
#include <cuda_bf16.h>
#include <cstdint>
#include <math.h>

#define N_ 128
#define D_ 512
#define L_ 512
#define K_ 512
#define M_ (N_ * D_)

// ---------------- device globals (allocation-free scratch) ----------------
__device__ float g_w[D_ * L_];                       // fp32 window * exp(sigma/(L-1))
__device__ __nv_bfloat16 gA_hi[(size_t)M_ * L_];     // 67 MB
__device__ __nv_bfloat16 gA_lo[(size_t)M_ * L_];     // 67 MB
__device__ __nv_bfloat16 gBc_hi[L_ * K_];
__device__ __nv_bfloat16 gBc_lo[L_ * K_];
__device__ __nv_bfloat16 gBs_hi[L_ * K_];
__device__ __nv_bfloat16 gBs_lo[L_ * K_];

// ---------------- helpers ----------------
__device__ __forceinline__ uint32_t smem_u32(const void* p) {
    uint32_t a;
    asm("{ .reg .u64 t; cvta.to.shared.u64 t, %1; cvt.u32.u64 %0, t; }" : "=r"(a) : "l"(p));
    return a;
}
#define CP_ASYNC16(dst, src) asm volatile("cp.async.cg.shared.global [%0], [%1], 16;" :: "r"(dst), "l"(src))
#define CP_COMMIT() asm volatile("cp.async.commit_group;" ::: "memory")

#define LDSM4(R, addr) \
    asm volatile("ldmatrix.sync.aligned.m8n8.x4.shared.b16 {%0,%1,%2,%3}, [%4];" \
        : "=r"((R)[0]), "=r"((R)[1]), "=r"((R)[2]), "=r"((R)[3]) : "r"(addr))
#define LDSM4T(R, addr) \
    asm volatile("ldmatrix.sync.aligned.m8n8.x4.trans.shared.b16 {%0,%1,%2,%3}, [%4];" \
        : "=r"((R)[0]), "=r"((R)[1]), "=r"((R)[2]), "=r"((R)[3]) : "r"(addr))

#define MMA16816(D, A, B0, B1) \
    asm volatile("mma.sync.aligned.m16n8k16.row.col.f32.bf16.bf16.f32 " \
        "{%0,%1,%2,%3}, {%4,%5,%6,%7}, {%8,%9}, {%0,%1,%2,%3};" \
        : "+f"((D)[0]), "+f"((D)[1]), "+f"((D)[2]), "+f"((D)[3]) \
        : "r"((A)[0]), "r"((A)[1]), "r"((A)[2]), "r"((A)[3]), "r"(B0), "r"(B1))

// ---------------- prep 1: basis (split bf16) + window (fp32) ----------------
__global__ void precompute_kernel(const float* __restrict__ a,
                                  const float* __restrict__ sigma) {
    const int idx = blockIdx.x * blockDim.x + threadIdx.x;
    const float c = (float)(6.283185307179586 / 511.0);
    if (idx < L_ * K_) {
        const int l = idx / K_, k = idx - l * K_;
        float s, cc;
        sincosf(c * (float)(l * k), &s, &cc);
        __nv_bfloat16 ch = __float2bfloat16(cc);
        __nv_bfloat16 sh = __float2bfloat16(s);
        gBc_hi[idx] = ch;
        gBc_lo[idx] = __float2bfloat16(cc - __bfloat162float(ch));
        gBs_hi[idx] = sh;
        gBs_lo[idx] = __float2bfloat16(s - __bfloat162float(sh));
    }
    if (idx < D_ * L_) {
        const int d = idx / L_, l = idx - d * L_;
        const float ad = a[d];
        const float w = ad - (1.0f - ad) * cosf(c * (float)l);
        g_w[idx] = w * expf(sigma[d] * (1.0f / 511.0f));
    }
}

// ---------------- prep 2: xw = x * w, split to bf16 hi/lo ----------------
__global__ __launch_bounds__(256)
void split_a_kernel(const float4* __restrict__ x) {
    const size_t g = (size_t)blockIdx.x * blockDim.x + threadIdx.x;
    if (g >= (size_t)M_ * L_ / 4) return;
    const int m  = (int)(g >> 7);
    const int l4 = (int)(g & 127);
    const int d  = m & (D_ - 1);
    const float4 xv = x[g];
    const float4 wv = *(const float4*)(g_w + (size_t)d * L_ + l4 * 4);
    float v[4] = {xv.x * wv.x, xv.y * wv.y, xv.z * wv.z, xv.w * wv.w};
    __nv_bfloat16 hi[4], lo[4];
#pragma unroll
    for (int i = 0; i < 4; ++i) {
        hi[i] = __float2bfloat16(v[i]);
        lo[i] = __float2bfloat16(v[i] - __bfloat162float(hi[i]));
    }
    ((uint2*)gA_hi)[g] = *(uint2*)hi;
    ((uint2*)gA_lo)[g] = *(uint2*)lo;
}

// ---------------- main: mma.sync dual-GEMM + magnitude ----------------
// CTA tile: 128(M) x 64(N), BK=64, 8 warps (2 in M x 4 in N), warp tile 64x16.
// 3-term bf16 split: Xr += Ah*Ch + Al*Ch + Ah*Cl (drop Al*Cl), same for Xi.
#define BK 64
#define NCH (L_ / BK)            // 8 chunks
#define PITCH 144                // 128B data + 16B pad (conflict-free ldmatrix)
#define SA_BYTES (128 * PITCH)   // 18432 per A matrix
#define SB_BYTES (64 * PITCH)    // 9216 per B matrix
#define SB_BASE (2 * SA_BYTES)   // 36864
#define STAGE (SB_BASE + 4 * SB_BYTES)  // 73728
#define SMEM_TOTAL (2 * STAGE)          // 147456

__device__ __forceinline__ void load_chunk(uint32_t sbuf, int row0, int col0,
                                           int l0, int tid) {
    // A: 2 matrices x 128 rows x 8 (16B units)
#pragma unroll
    for (int p = 0; p < 8; ++p) {
        const int u = tid + p * 256;
        const int mat = u >> 10;
        const int r = (u >> 3) & 127;
        const int cu = u & 7;
        const __nv_bfloat16* g = mat ? gA_lo : gA_hi;
        const __nv_bfloat16* src = g + (size_t)(row0 + r) * L_ + l0 + cu * 8;
        CP_ASYNC16(sbuf + mat * SA_BYTES + r * PITCH + cu * 16, src);
    }
    // B: 4 matrices x 64 rows x 8 (16B units)
    const __nv_bfloat16* mats[4] = {gBc_hi, gBc_lo, gBs_hi, gBs_lo};
#pragma unroll
    for (int p = 0; p < 8; ++p) {
        const int u = tid + p * 256;
        const int mat = u >> 9;
        const int r = (u >> 3) & 63;
        const int cu = u & 7;
        const __nv_bfloat16* src = mats[mat] + (size_t)(l0 + r) * K_ + col0 + cu * 8;
        CP_ASYNC16(sbuf + SB_BASE + mat * SB_BYTES + r * PITCH + cu * 16, src);
    }
}

__global__ __launch_bounds__(256, 1)
void spectro_mma_kernel(float* __restrict__ out) {
    extern __shared__ char smem[];
    const uint32_t sbase = smem_u32(smem);
    const int tid = threadIdx.x;
    const int wid = tid >> 5;
    const int lid = tid & 31;
    const int col0 = blockIdx.x * 64;    // 8 col tiles
    const int row0 = blockIdx.y * 128;   // 512 row tiles
    const int wm = wid >> 2;             // 0..1 (M)
    const int wn = wid & 3;              // 0..3 (N)

    float accR[4][2][4];
    float accI[4][2][4];
#pragma unroll
    for (int mt = 0; mt < 4; ++mt)
#pragma unroll
        for (int nt = 0; nt < 2; ++nt)
#pragma unroll
            for (int j = 0; j < 4; ++j) { accR[mt][nt][j] = 0.f; accI[mt][nt][j] = 0.f; }

    // ldmatrix lane addressing
    const int g8 = lid >> 3;       // 0..3
    const int lr = lid & 7;        // row within 8x8

    load_chunk(sbase, row0, col0, 0, tid);
    CP_COMMIT();

    for (int c = 0; c < NCH; ++c) {
        if (c + 1 < NCH) {
            load_chunk(sbase + ((c + 1) & 1) * STAGE, row0, col0, (c + 1) * BK, tid);
            CP_COMMIT();
            asm volatile("cp.async.wait_group 1;" ::: "memory");
        } else {
            asm volatile("cp.async.wait_group 0;" ::: "memory");
        }
        __syncthreads();

        const uint32_t sa = sbase + (c & 1) * STAGE;
        const uint32_t sb = sa + SB_BASE;
#pragma unroll
        for (int kk = 0; kk < 4; ++kk) {
            // A fragments (hi & lo), 4 m-tiles of 16
            uint32_t aH[4][4], aL[4][4];
#pragma unroll
            for (int mt = 0; mt < 4; ++mt) {
                const int row = wm * 64 + mt * 16 + ((g8 & 1) << 3) + lr;
                const uint32_t ad = sa + row * PITCH + kk * 32 + ((g8 >> 1) << 4);
                LDSM4(aH[mt], ad);
                LDSM4(aL[mt], ad + SA_BYTES);
            }
            // B fragments: 4 matrices, 2 n-tiles each (x4.trans)
            const int krow = kk * 16 + ((g8 & 1) << 3) + lr;
            const uint32_t bd = sb + krow * PITCH + wn * 32 + ((g8 >> 1) << 4);
            uint32_t bCh[4], bCl[4], bSh[4], bSl[4];
            LDSM4T(bCh, bd);
            LDSM4T(bCl, bd + 1 * SB_BYTES);
            LDSM4T(bSh, bd + 2 * SB_BYTES);
            LDSM4T(bSl, bd + 3 * SB_BYTES);
#pragma unroll
            for (int mt = 0; mt < 4; ++mt) {
#pragma unroll
                for (int nt = 0; nt < 2; ++nt) {
                    MMA16816(accR[mt][nt], aH[mt], bCh[nt * 2], bCh[nt * 2 + 1]);
                    MMA16816(accI[mt][nt], aH[mt], bSh[nt * 2], bSh[nt * 2 + 1]);
                    MMA16816(accR[mt][nt], aL[mt], bCh[nt * 2], bCh[nt * 2 + 1]);
                    MMA16816(accI[mt][nt], aL[mt], bSh[nt * 2], bSh[nt * 2 + 1]);
                    MMA16816(accR[mt][nt], aH[mt], bCl[nt * 2], bCl[nt * 2 + 1]);
                    MMA16816(accI[mt][nt], aH[mt], bSl[nt * 2], bSl[nt * 2 + 1]);
                }
            }
        }
        __syncthreads();
    }

    // ---- epilogue: magnitude, direct from accumulator fragments ----
#pragma unroll
    for (int mt = 0; mt < 4; ++mt) {
#pragma unroll
        for (int nt = 0; nt < 2; ++nt) {
            const int r0 = row0 + wm * 64 + mt * 16 + (lid >> 2);
            const int cc = col0 + wn * 16 + nt * 8 + (lid & 3) * 2;
            float2 o0, o1;
            o0.x = sqrtf(fmaf(accR[mt][nt][0], accR[mt][nt][0],
                              accI[mt][nt][0] * accI[mt][nt][0]));
            o0.y = sqrtf(fmaf(accR[mt][nt][1], accR[mt][nt][1],
                              accI[mt][nt][1] * accI[mt][nt][1]));
            o1.x = sqrtf(fmaf(accR[mt][nt][2], accR[mt][nt][2],
                              accI[mt][nt][2] * accI[mt][nt][2]));
            o1.y = sqrtf(fmaf(accR[mt][nt][3], accR[mt][nt][3],
                              accI[mt][nt][3] * accI[mt][nt][3]));
            *(float2*)(out + (size_t)r0 * K_ + cc) = o0;
            *(float2*)(out + (size_t)(r0 + 8) * K_ + cc) = o1;
        }
    }
}

// ---------------------------------------------------------------------------
extern "C" void kernel_launch(void* const* d_in, const int* in_sizes, int n_in,
                              void* d_out, int out_size) {
    const float* x     = (const float*)d_in[0];  // (N, D, L)
    const float* a     = (const float*)d_in[1];  // (D,)
    const float* sigma = (const float*)d_in[2];  // (D,)
    float* out = (float*)d_out;                  // (N, D, K)

    precompute_kernel<<<(L_ * K_ + 255) / 256, 256>>>(a, sigma);
    split_a_kernel<<<(M_ * L_ / 4 + 255) / 256, 256>>>((const float4*)x);

    static bool attr_set = false;
    if (!attr_set) {
        cudaFuncSetAttribute(spectro_mma_kernel,
                             cudaFuncAttributeMaxDynamicSharedMemorySize, SMEM_TOTAL);
        attr_set = true;
    }
    dim3 grid(K_ / 64, M_ / 128);   // (8, 512)
    spectro_mma_kernel<<<grid, 256, SMEM_TOTAL>>>(out);
}

// round 8
// speedup vs baseline: 3.0415x; 1.3450x over previous
#include <cuda_runtime.h>
#include <cuda_fp16.h>
#include <cstdint>
#include <math.h>

#define N_ 128
#define D_ 512
#define L_ 512
#define K_ 512
#define M_ (N_ * D_)

// ---------------- device globals (allocation-free scratch) ----------------
__device__ float g_w[D_ * L_];                 // fp32 window * exp(sigma/(L-1))
__device__ __half gA_hi[(size_t)M_ * L_];      // 67 MB
__device__ __half gA_lo[(size_t)M_ * L_];      // 67 MB
__device__ __half gBc[L_ * K_];                // cos basis, single fp16
__device__ __half gBs[L_ * K_];                // sin basis, single fp16

// ---------------- helpers ----------------
__device__ __forceinline__ uint32_t smem_u32(const void* p) {
    uint32_t a;
    asm("{ .reg .u64 t; cvta.to.shared.u64 t, %1; cvt.u32.u64 %0, t; }" : "=r"(a) : "l"(p));
    return a;
}
#define CP_ASYNC16(dst, src) asm volatile("cp.async.cg.shared.global [%0], [%1], 16;" :: "r"(dst), "l"(src))
#define CP_COMMIT() asm volatile("cp.async.commit_group;" ::: "memory")

#define LDSM4(R, addr) \
    asm volatile("ldmatrix.sync.aligned.m8n8.x4.shared.b16 {%0,%1,%2,%3}, [%4];" \
        : "=r"((R)[0]), "=r"((R)[1]), "=r"((R)[2]), "=r"((R)[3]) : "r"(addr))
#define LDSM4T(R, addr) \
    asm volatile("ldmatrix.sync.aligned.m8n8.x4.trans.shared.b16 {%0,%1,%2,%3}, [%4];" \
        : "=r"((R)[0]), "=r"((R)[1]), "=r"((R)[2]), "=r"((R)[3]) : "r"(addr))

#define MMA16816(D, A, B0, B1) \
    asm volatile("mma.sync.aligned.m16n8k16.row.col.f32.f16.f16.f32 " \
        "{%0,%1,%2,%3}, {%4,%5,%6,%7}, {%8,%9}, {%0,%1,%2,%3};" \
        : "+f"((D)[0]), "+f"((D)[1]), "+f"((D)[2]), "+f"((D)[3]) \
        : "r"((A)[0]), "r"((A)[1]), "r"((A)[2]), "r"((A)[3]), "r"(B0), "r"(B1))

// ---------------- prep 1: basis (fp16) + window (fp32) ----------------
__global__ void precompute_kernel(const float* __restrict__ a,
                                  const float* __restrict__ sigma) {
    const int idx = blockIdx.x * blockDim.x + threadIdx.x;
    const float c = (float)(6.283185307179586 / 511.0);
    if (idx < L_ * K_) {
        const int l = idx / K_, k = idx - l * K_;
        float s, cc;
        sincosf(c * (float)(l * k), &s, &cc);
        gBc[idx] = __float2half(cc);
        gBs[idx] = __float2half(s);
    }
    if (idx < D_ * L_) {
        const int d = idx / L_, l = idx - d * L_;
        const float ad = a[d];
        const float w = ad - (1.0f - ad) * cosf(c * (float)l);
        g_w[idx] = w * expf(sigma[d] * (1.0f / 511.0f));
    }
}

// ---------------- prep 2: xw = x * w, split to fp16 hi/lo ----------------
__global__ __launch_bounds__(256)
void split_a_kernel(const float4* __restrict__ x) {
    const size_t g = (size_t)blockIdx.x * blockDim.x + threadIdx.x;
    if (g >= (size_t)M_ * L_ / 4) return;
    const int m  = (int)(g >> 7);
    const int l4 = (int)(g & 127);
    const int d  = m & (D_ - 1);
    const float4 xv = x[g];
    const float4 wv = *(const float4*)(g_w + (size_t)d * L_ + l4 * 4);
    float v[4] = {xv.x * wv.x, xv.y * wv.y, xv.z * wv.z, xv.w * wv.w};
    __half hi[4], lo[4];
#pragma unroll
    for (int i = 0; i < 4; ++i) {
        hi[i] = __float2half(v[i]);
        lo[i] = __float2half(v[i] - __half2float(hi[i]));
    }
    ((uint2*)gA_hi)[g] = *(uint2*)hi;
    ((uint2*)gA_lo)[g] = *(uint2*)lo;
}

// ---------------- main: mma.sync dual-GEMM + magnitude ----------------
// CTA tile: 128(M) x 64(N), BK=64, 8 warps (2 in M x 4 in N), warp tile 64x16.
// 2-term fp16 split on A only: Xr += Ah*C + Al*C ; Xi += Ah*S + Al*S.
#define BK 64
#define NCH (L_ / BK)            // 8 chunks
#define NSTAGE 3
#define PITCH 144                // 128B data + 16B pad (conflict-free ldmatrix)
#define SA_BYTES (128 * PITCH)   // 18432 per A matrix
#define SB_BYTES (64 * PITCH)    // 9216 per B matrix
#define SB_BASE (2 * SA_BYTES)   // 36864
#define STAGE (SB_BASE + 2 * SB_BYTES)  // 55296
#define SMEM_TOTAL (NSTAGE * STAGE)     // 165888

__device__ __forceinline__ void load_chunk(uint32_t sbuf, int row0, int col0,
                                           int l0, int tid) {
    // A: 2 matrices x 128 rows x 8 (16B units) = 2048 -> 8 per thread
#pragma unroll
    for (int p = 0; p < 8; ++p) {
        const int u = tid + p * 256;
        const int mat = u >> 10;
        const int r = (u >> 3) & 127;
        const int cu = u & 7;
        const __half* g = mat ? gA_lo : gA_hi;
        const __half* src = g + (size_t)(row0 + r) * L_ + l0 + cu * 8;
        CP_ASYNC16(sbuf + mat * SA_BYTES + r * PITCH + cu * 16, src);
    }
    // B: 2 matrices x 64 rows x 8 (16B units) = 1024 -> 4 per thread
#pragma unroll
    for (int p = 0; p < 4; ++p) {
        const int u = tid + p * 256;
        const int mat = u >> 9;
        const int r = (u >> 3) & 63;
        const int cu = u & 7;
        const __half* g = mat ? gBs : gBc;
        const __half* src = g + (size_t)(l0 + r) * K_ + col0 + cu * 8;
        CP_ASYNC16(sbuf + SB_BASE + mat * SB_BYTES + r * PITCH + cu * 16, src);
    }
}

__global__ __launch_bounds__(256, 1)
void spectro_mma_kernel(float* __restrict__ out) {
    extern __shared__ char smem[];
    const uint32_t sbase = smem_u32(smem);
    const int tid = threadIdx.x;
    const int wid = tid >> 5;
    const int lid = tid & 31;
    const int col0 = blockIdx.x * 64;    // 8 col tiles
    const int row0 = blockIdx.y * 128;   // 512 row tiles
    const int wm = wid >> 2;             // 0..1 (M)
    const int wn = wid & 3;              // 0..3 (N)

    float accR[4][2][4];
    float accI[4][2][4];
#pragma unroll
    for (int mt = 0; mt < 4; ++mt)
#pragma unroll
        for (int nt = 0; nt < 2; ++nt)
#pragma unroll
            for (int j = 0; j < 4; ++j) { accR[mt][nt][j] = 0.f; accI[mt][nt][j] = 0.f; }

    const int g8 = lid >> 3;       // 0..3
    const int lr = lid & 7;        // row within 8x8

    // prologue: stages 0 and 1 in flight
    load_chunk(sbase + 0 * STAGE, row0, col0, 0, tid);
    CP_COMMIT();
    load_chunk(sbase + 1 * STAGE, row0, col0, BK, tid);
    CP_COMMIT();

    for (int c = 0; c < NCH; ++c) {
        if (c + 2 < NCH) {
            load_chunk(sbase + ((c + 2) % NSTAGE) * STAGE, row0, col0, (c + 2) * BK, tid);
            CP_COMMIT();
            asm volatile("cp.async.wait_group 2;" ::: "memory");
        } else if (c + 1 < NCH) {
            asm volatile("cp.async.wait_group 1;" ::: "memory");
        } else {
            asm volatile("cp.async.wait_group 0;" ::: "memory");
        }
        __syncthreads();   // chunk c data visible to all warps

        const uint32_t sa = sbase + (c % NSTAGE) * STAGE;
        const uint32_t sb = sa + SB_BASE;
#pragma unroll
        for (int kk = 0; kk < 4; ++kk) {
            // A fragments (hi & lo), 4 m-tiles of 16
            uint32_t aH[4][4], aL[4][4];
#pragma unroll
            for (int mt = 0; mt < 4; ++mt) {
                const int row = wm * 64 + mt * 16 + ((g8 & 1) << 3) + lr;
                const uint32_t ad = sa + row * PITCH + kk * 32 + ((g8 >> 1) << 4);
                LDSM4(aH[mt], ad);
                LDSM4(aL[mt], ad + SA_BYTES);
            }
            // B fragments: cos & sin, 2 n-tiles each (x4.trans)
            const int krow = kk * 16 + ((g8 & 1) << 3) + lr;
            const uint32_t bd = sb + krow * PITCH + wn * 32 + ((g8 >> 1) << 4);
            uint32_t bC[4], bS[4];
            LDSM4T(bC, bd);
            LDSM4T(bS, bd + SB_BYTES);
#pragma unroll
            for (int mt = 0; mt < 4; ++mt) {
#pragma unroll
                for (int nt = 0; nt < 2; ++nt) {
                    MMA16816(accR[mt][nt], aH[mt], bC[nt * 2], bC[nt * 2 + 1]);
                    MMA16816(accI[mt][nt], aH[mt], bS[nt * 2], bS[nt * 2 + 1]);
                    MMA16816(accR[mt][nt], aL[mt], bC[nt * 2], bC[nt * 2 + 1]);
                    MMA16816(accI[mt][nt], aL[mt], bS[nt * 2], bS[nt * 2 + 1]);
                }
            }
        }
        __syncthreads();   // all warps done reading before this slot is reloaded
    }

    // ---- epilogue: magnitude, direct from accumulator fragments ----
#pragma unroll
    for (int mt = 0; mt < 4; ++mt) {
#pragma unroll
        for (int nt = 0; nt < 2; ++nt) {
            const int r0 = row0 + wm * 64 + mt * 16 + (lid >> 2);
            const int cc = col0 + wn * 16 + nt * 8 + (lid & 3) * 2;
            float2 o0, o1;
            o0.x = sqrtf(fmaf(accR[mt][nt][0], accR[mt][nt][0],
                              accI[mt][nt][0] * accI[mt][nt][0]));
            o0.y = sqrtf(fmaf(accR[mt][nt][1], accR[mt][nt][1],
                              accI[mt][nt][1] * accI[mt][nt][1]));
            o1.x = sqrtf(fmaf(accR[mt][nt][2], accR[mt][nt][2],
                              accI[mt][nt][2] * accI[mt][nt][2]));
            o1.y = sqrtf(fmaf(accR[mt][nt][3], accR[mt][nt][3],
                              accI[mt][nt][3] * accI[mt][nt][3]));
            *(float2*)(out + (size_t)r0 * K_ + cc) = o0;
            *(float2*)(out + (size_t)(r0 + 8) * K_ + cc) = o1;
        }
    }
}

// ---------------------------------------------------------------------------
extern "C" void kernel_launch(void* const* d_in, const int* in_sizes, int n_in,
                              void* d_out, int out_size) {
    const float* x     = (const float*)d_in[0];  // (N, D, L)
    const float* a     = (const float*)d_in[1];  // (D,)
    const float* sigma = (const float*)d_in[2];  // (D,)
    float* out = (float*)d_out;                  // (N, D, K)

    precompute_kernel<<<(L_ * K_ + 255) / 256, 256>>>(a, sigma);
    split_a_kernel<<<(M_ * L_ / 4 + 255) / 256, 256>>>((const float4*)x);

    static bool attr_set = false;
    if (!attr_set) {
        cudaFuncSetAttribute(spectro_mma_kernel,
                             cudaFuncAttributeMaxDynamicSharedMemorySize, SMEM_TOTAL);
        attr_set = true;
    }
    dim3 grid(K_ / 64, M_ / 128);   // (8, 512)
    spectro_mma_kernel<<<grid, 256, SMEM_TOTAL>>>(out);
}

// round 9
// speedup vs baseline: 5.9672x; 1.9619x over previous
#include <cuda_runtime.h>
#include <cuda_fp16.h>
#include <cstdint>
#include <math.h>

#define N_ 128
#define D_ 512
#define L_ 512
#define K_ 512
#define M_ (N_ * D_)

// ---------------- device globals (allocation-free scratch) ----------------
__device__ float g_w[D_ * L_];                 // fp32 window * exp(sigma/(L-1))
__device__ __half gA[(size_t)M_ * L_];         // 67 MB, xw in fp16
__device__ __half gBc[L_ * K_];                // cos basis, fp16
__device__ __half gBs[L_ * K_];                // sin basis, fp16

// ---------------- helpers ----------------
__device__ __forceinline__ uint32_t smem_u32(const void* p) {
    uint32_t a;
    asm("{ .reg .u64 t; cvta.to.shared.u64 t, %1; cvt.u32.u64 %0, t; }" : "=r"(a) : "l"(p));
    return a;
}
#define CP_ASYNC16(dst, src) asm volatile("cp.async.cg.shared.global [%0], [%1], 16;" :: "r"(dst), "l"(src))
#define CP_COMMIT() asm volatile("cp.async.commit_group;" ::: "memory")

#define LDSM4(R, addr) \
    asm volatile("ldmatrix.sync.aligned.m8n8.x4.shared.b16 {%0,%1,%2,%3}, [%4];" \
        : "=r"((R)[0]), "=r"((R)[1]), "=r"((R)[2]), "=r"((R)[3]) : "r"(addr))
#define LDSM4T(R, addr) \
    asm volatile("ldmatrix.sync.aligned.m8n8.x4.trans.shared.b16 {%0,%1,%2,%3}, [%4];" \
        : "=r"((R)[0]), "=r"((R)[1]), "=r"((R)[2]), "=r"((R)[3]) : "r"(addr))

#define MMA16816(D, A, B0, B1) \
    asm volatile("mma.sync.aligned.m16n8k16.row.col.f32.f16.f16.f32 " \
        "{%0,%1,%2,%3}, {%4,%5,%6,%7}, {%8,%9}, {%0,%1,%2,%3};" \
        : "+f"((D)[0]), "+f"((D)[1]), "+f"((D)[2]), "+f"((D)[3]) \
        : "r"((A)[0]), "r"((A)[1]), "r"((A)[2]), "r"((A)[3]), "r"(B0), "r"(B1))

// ---------------- prep 1: basis (fp16) + window (fp32) ----------------
__global__ void precompute_kernel(const float* __restrict__ a,
                                  const float* __restrict__ sigma) {
    const int idx = blockIdx.x * blockDim.x + threadIdx.x;
    const float c = (float)(6.283185307179586 / 511.0);
    if (idx < L_ * K_) {
        const int l = idx / K_, k = idx - l * K_;
        float s, cc;
        sincosf(c * (float)(l * k), &s, &cc);
        gBc[idx] = __float2half(cc);
        gBs[idx] = __float2half(s);
    }
    if (idx < D_ * L_) {
        const int d = idx / L_, l = idx - d * L_;
        const float ad = a[d];
        const float w = ad - (1.0f - ad) * cosf(c * (float)l);
        g_w[idx] = w * expf(sigma[d] * (1.0f / 511.0f));
    }
}

// ---------------- prep 2: xw = x * w -> fp16 ----------------
__global__ __launch_bounds__(256)
void split_a_kernel(const float4* __restrict__ x) {
    const size_t g = (size_t)blockIdx.x * blockDim.x + threadIdx.x;
    if (g >= (size_t)M_ * L_ / 4) return;
    const int m  = (int)(g >> 7);
    const int l4 = (int)(g & 127);
    const int d  = m & (D_ - 1);
    const float4 xv = x[g];
    const float4 wv = *(const float4*)(g_w + (size_t)d * L_ + l4 * 4);
    __half h[4];
    h[0] = __float2half(xv.x * wv.x);
    h[1] = __float2half(xv.y * wv.y);
    h[2] = __float2half(xv.z * wv.z);
    h[3] = __float2half(xv.w * wv.w);
    ((uint2*)gA)[g] = *(uint2*)h;
}

// ---------------- main: mma.sync dual-GEMM + magnitude ----------------
// CTA tile: 128(M) x 64(N), BK=64, 8 warps (2 in M x 4 in N), warp tile 64x16.
// Single fp16 A term: Xr += A*C ; Xi += A*S.
#define BK 64
#define NCH (L_ / BK)            // 8 chunks
#define NSTAGE 2
#define PITCH 144                // 128B data + 16B pad (conflict-free ldmatrix)
#define SA_BYTES (128 * PITCH)   // 18432 (A tile)
#define SB_BYTES (64 * PITCH)    // 9216 per B matrix
#define SB_BASE SA_BYTES
#define STAGE (SA_BYTES + 2 * SB_BYTES)  // 36864
#define SMEM_TOTAL (NSTAGE * STAGE)      // 73728 -> 2 CTAs/SM

__device__ __forceinline__ void load_chunk(uint32_t sbuf, int row0, int col0,
                                           int l0, int tid) {
    // A: 128 rows x 8 (16B units) = 1024 -> 4 per thread
#pragma unroll
    for (int p = 0; p < 4; ++p) {
        const int u = tid + p * 256;
        const int r = u >> 3;
        const int cu = u & 7;
        const __half* src = gA + (size_t)(row0 + r) * L_ + l0 + cu * 8;
        CP_ASYNC16(sbuf + r * PITCH + cu * 16, src);
    }
    // B: 2 matrices x 64 rows x 8 (16B units) = 1024 -> 4 per thread
#pragma unroll
    for (int p = 0; p < 4; ++p) {
        const int u = tid + p * 256;
        const int mat = u >> 9;
        const int r = (u >> 3) & 63;
        const int cu = u & 7;
        const __half* g = mat ? gBs : gBc;
        const __half* src = g + (size_t)(l0 + r) * K_ + col0 + cu * 8;
        CP_ASYNC16(sbuf + SB_BASE + mat * SB_BYTES + r * PITCH + cu * 16, src);
    }
}

__global__ __launch_bounds__(256, 2)
void spectro_mma_kernel(float* __restrict__ out) {
    extern __shared__ char smem[];
    const uint32_t sbase = smem_u32(smem);
    const int tid = threadIdx.x;
    const int wid = tid >> 5;
    const int lid = tid & 31;
    const int col0 = blockIdx.x * 64;    // 8 col tiles
    const int row0 = blockIdx.y * 128;   // 512 row tiles
    const int wm = wid >> 2;             // 0..1 (M)
    const int wn = wid & 3;              // 0..3 (N)

    float accR[4][2][4];
    float accI[4][2][4];
#pragma unroll
    for (int mt = 0; mt < 4; ++mt)
#pragma unroll
        for (int nt = 0; nt < 2; ++nt)
#pragma unroll
            for (int j = 0; j < 4; ++j) { accR[mt][nt][j] = 0.f; accI[mt][nt][j] = 0.f; }

    const int g8 = lid >> 3;       // 0..3
    const int lr = lid & 7;        // row within 8x8

    load_chunk(sbase, row0, col0, 0, tid);
    CP_COMMIT();

    for (int c = 0; c < NCH; ++c) {
        if (c + 1 < NCH) {
            load_chunk(sbase + ((c + 1) & 1) * STAGE, row0, col0, (c + 1) * BK, tid);
            CP_COMMIT();
            asm volatile("cp.async.wait_group 1;" ::: "memory");
        } else {
            asm volatile("cp.async.wait_group 0;" ::: "memory");
        }
        __syncthreads();

        const uint32_t sa = sbase + (c & 1) * STAGE;
        const uint32_t sb = sa + SB_BASE;
#pragma unroll
        for (int kk = 0; kk < 4; ++kk) {
            uint32_t aH[4][4];
#pragma unroll
            for (int mt = 0; mt < 4; ++mt) {
                const int row = wm * 64 + mt * 16 + ((g8 & 1) << 3) + lr;
                const uint32_t ad = sa + row * PITCH + kk * 32 + ((g8 >> 1) << 4);
                LDSM4(aH[mt], ad);
            }
            const int krow = kk * 16 + ((g8 & 1) << 3) + lr;
            const uint32_t bd = sb + krow * PITCH + wn * 32 + ((g8 >> 1) << 4);
            uint32_t bC[4], bS[4];
            LDSM4T(bC, bd);
            LDSM4T(bS, bd + SB_BYTES);
#pragma unroll
            for (int mt = 0; mt < 4; ++mt) {
#pragma unroll
                for (int nt = 0; nt < 2; ++nt) {
                    MMA16816(accR[mt][nt], aH[mt], bC[nt * 2], bC[nt * 2 + 1]);
                    MMA16816(accI[mt][nt], aH[mt], bS[nt * 2], bS[nt * 2 + 1]);
                }
            }
        }
        __syncthreads();
    }

    // ---- epilogue: magnitude, direct from accumulator fragments ----
#pragma unroll
    for (int mt = 0; mt < 4; ++mt) {
#pragma unroll
        for (int nt = 0; nt < 2; ++nt) {
            const int r0 = row0 + wm * 64 + mt * 16 + (lid >> 2);
            const int cc = col0 + wn * 16 + nt * 8 + (lid & 3) * 2;
            float2 o0, o1;
            o0.x = sqrtf(fmaf(accR[mt][nt][0], accR[mt][nt][0],
                              accI[mt][nt][0] * accI[mt][nt][0]));
            o0.y = sqrtf(fmaf(accR[mt][nt][1], accR[mt][nt][1],
                              accI[mt][nt][1] * accI[mt][nt][1]));
            o1.x = sqrtf(fmaf(accR[mt][nt][2], accR[mt][nt][2],
                              accI[mt][nt][2] * accI[mt][nt][2]));
            o1.y = sqrtf(fmaf(accR[mt][nt][3], accR[mt][nt][3],
                              accI[mt][nt][3] * accI[mt][nt][3]));
            *(float2*)(out + (size_t)r0 * K_ + cc) = o0;
            *(float2*)(out + (size_t)(r0 + 8) * K_ + cc) = o1;
        }
    }
}

// ---------------------------------------------------------------------------
extern "C" void kernel_launch(void* const* d_in, const int* in_sizes, int n_in,
                              void* d_out, int out_size) {
    const float* x     = (const float*)d_in[0];  // (N, D, L)
    const float* a     = (const float*)d_in[1];  // (D,)
    const float* sigma = (const float*)d_in[2];  // (D,)
    float* out = (float*)d_out;                  // (N, D, K)

    precompute_kernel<<<(L_ * K_ + 255) / 256, 256>>>(a, sigma);
    split_a_kernel<<<(M_ * L_ / 4 + 255) / 256, 256>>>((const float4*)x);

    static bool attr_set = false;
    if (!attr_set) {
        cudaFuncSetAttribute(spectro_mma_kernel,
                             cudaFuncAttributeMaxDynamicSharedMemorySize, SMEM_TOTAL);
        attr_set = true;
    }
    dim3 grid(K_ / 64, M_ / 128);   // (8, 512)
    spectro_mma_kernel<<<grid, 256, SMEM_TOTAL>>>(out);
}